// round 1
// baseline (speedup 1.0000x reference)
#include <cuda_runtime.h>
#include <math.h>

#define NIMG 4
#define CC 15
#define KLOC 65536            // H*W
#define KC (KLOC*CC)          // 983040
#define TOPK 400
#define POSTN 100
#define NBINS 8192
#define CAP 16384
#define NWORDS 13             // ceil(400/32)
#define CAND_LOGIT (-2.9444389791664403f)   // logit(0.05)

// ---------------- scratch (device globals; no allocations) ----------------
__device__ float              g_ctr[NIMG*KLOC];
__device__ unsigned int       g_hist[NIMG*NBINS];
__device__ int                g_cnt[NIMG];
__device__ unsigned int       g_thresh[NIMG];
__device__ unsigned long long g_cand[NIMG*CAP];
__device__ unsigned long long g_top[NIMG*TOPK];
__device__ float              g_corners[NIMG*TOPK*8];
__device__ float4             g_meta[NIMG*TOPK];     // cx, cy, radius, area
__device__ float              g_score[NIMG*TOPK];
__device__ int                g_label[NIMG*TOPK];
__device__ int                g_valid[NIMG*TOPK];
__device__ unsigned int       g_sup[NIMG*TOPK*NWORDS];

__device__ __forceinline__ float sigmoidf_(float x){ return 1.0f/(1.0f+expf(-x)); }

// ---------------- K0: init (sigmoid centerness, zero hist/cnt) ----------------
__global__ void kInit(const float* __restrict__ ctr) {
    int i = blockIdx.x*blockDim.x + threadIdx.x;
    if (i < NIMG*KLOC)  g_ctr[i]  = sigmoidf_(ctr[i]);
    if (i < NIMG*NBINS) g_hist[i] = 0u;
    if (i < NIMG)       g_cnt[i]  = 0;
}

// ---------------- K1: histogram of comb score bits ----------------
__global__ void kHist(const float* __restrict__ cls) {
    __shared__ unsigned int sh[NBINS];
    for (int i = threadIdx.x; i < NBINS; i += blockDim.x) sh[i] = 0u;
    __syncthreads();
    int n = blockIdx.y;
    const float* base = cls + (size_t)n*KC;
    const float* ctrb = g_ctr + n*KLOC;
    int e0 = blockIdx.x*4096 + threadIdx.x;
    #pragma unroll
    for (int q = 0; q < 16; q++) {
        int e = e0 + q*256;
        float x = base[e];
        if (x > CAND_LOGIT) {
            float comb = sigmoidf_(x) * ctrb[e & (KLOC-1)];
            atomicAdd(&sh[__float_as_uint(comb) >> 17], 1u);
        }
    }
    __syncthreads();
    for (int i = threadIdx.x; i < NBINS; i += blockDim.x)
        if (sh[i]) atomicAdd(&g_hist[n*NBINS + i], sh[i]);
}

// ---------------- K2: find bin containing 400th largest ----------------
__global__ void kThresh() {
    int n = blockIdx.x, t = threadIdx.x;   // 256 threads
    __shared__ unsigned int csum[256];
    __shared__ int s_found;
    __shared__ unsigned int s_B;
    const unsigned int* h = g_hist + n*NBINS;
    int hi = NBINS - 1 - t*32;
    unsigned int sum = 0;
    for (int b = hi; b > hi-32; b--) sum += h[b];
    csum[t] = sum;
    if (t == 0) { s_found = 0; s_B = 0u; }
    __syncthreads();
    for (int off = 1; off < 256; off <<= 1) {
        unsigned int v = (t >= off) ? csum[t-off] : 0u;
        __syncthreads();
        csum[t] += v;
        __syncthreads();
    }
    unsigned int incl = csum[t];
    unsigned int excl = incl - sum;
    if (excl < TOPK && incl >= TOPK) {
        unsigned int run = excl;
        for (int b = hi; b > hi-32; b--) {
            run += h[b];
            if (run >= TOPK) { s_B = (unsigned int)b; s_found = 1; break; }
        }
    }
    __syncthreads();
    if (t == 0) g_thresh[n] = (s_found ? s_B : 0u) << 17;
}

// ---------------- K3: collect survivors as composite keys ----------------
__global__ void kCollect(const float* __restrict__ cls) {
    int n = blockIdx.y;
    const float* base = cls + (size_t)n*KC;
    const float* ctrb = g_ctr + n*KLOC;
    unsigned int th = g_thresh[n];
    int e0 = blockIdx.x*4096 + threadIdx.x;
    #pragma unroll
    for (int q = 0; q < 16; q++) {
        int e = e0 + q*256;
        float x = base[e];
        if (x > CAND_LOGIT) {
            float comb = sigmoidf_(x) * ctrb[e & (KLOC-1)];
            unsigned int b = __float_as_uint(comb);
            if (b >= th) {
                int pos = atomicAdd(&g_cnt[n], 1);
                if (pos < CAP) {
                    unsigned int flat = (unsigned int)(e & (KLOC-1))*CC + (unsigned int)(e >> 16);
                    g_cand[n*CAP + pos] =
                        ((unsigned long long)b << 32) |
                        (unsigned long long)(0xFFFFFFFFu - flat);
                }
            }
        }
    }
}

// ---------------- K4: bitonic sort survivors (desc), emit top-400 ----------------
extern __shared__ unsigned long long s_keys[];
__global__ void kSort() {
    int n = blockIdx.x;
    int cnt = g_cnt[n]; if (cnt > CAP) cnt = CAP;
    int m = 512;
    while (m < cnt) m <<= 1;
    for (int i = threadIdx.x; i < m; i += blockDim.x)
        s_keys[i] = (i < cnt) ? g_cand[n*CAP + i] : 0ull;
    __syncthreads();
    for (int k = 2; k <= m; k <<= 1) {
        for (int jj = k >> 1; jj > 0; jj >>= 1) {
            for (int i = threadIdx.x; i < m; i += blockDim.x) {
                int l = i ^ jj;
                if (l > i) {
                    unsigned long long a = s_keys[i], b = s_keys[l];
                    bool desc = ((i & k) == 0);
                    if (desc ? (a < b) : (a > b)) { s_keys[i] = b; s_keys[l] = a; }
                }
            }
            __syncthreads();
        }
    }
    for (int i = threadIdx.x; i < TOPK; i += blockDim.x)
        g_top[n*TOPK + i] = s_keys[i];   // m >= 512 > TOPK always
}

// ---------------- K5: decode boxes (1 warp per candidate; warp argmax angle) ----------------
__global__ void kDecode(const float* __restrict__ angle,
                        const float* __restrict__ reg,
                        const float* __restrict__ anchors) {
    int n = blockIdx.y;
    int warp = threadIdx.x >> 5, lane = threadIdx.x & 31;
    int j = blockIdx.x*8 + warp;
    if (j >= TOPK) return;
    unsigned long long key = g_top[n*TOPK + j];
    unsigned int bits = (unsigned int)(key >> 32);
    float topv = __uint_as_float(bits);
    bool valid = topv > 0.0f;
    unsigned int flat = 0xFFFFFFFFu - (unsigned int)(key & 0xFFFFFFFFull);
    int loc = valid ? (int)(flat / CC) : 0;
    int cls = valid ? (int)(flat % CC) : 0;

    float bv = -3.402823466e38f; int bi = 1 << 20;
    if (valid) {
        const float* ap = angle + (size_t)n*90*KLOC + loc;
        #pragma unroll
        for (int s = 0; s < 3; s++) {
            int b = lane + 32*s;
            if (b < 90) {
                float v = __ldg(ap + (size_t)b*KLOC);
                if (v > bv) { bv = v; bi = b; }   // strict > keeps first occurrence per lane
            }
        }
    }
    #pragma unroll
    for (int off = 16; off; off >>= 1) {
        float ov = __shfl_xor_sync(0xffffffffu, bv, off);
        int   oi = __shfl_xor_sync(0xffffffffu, bi, off);
        if (ov > bv || (ov == bv && oi < bi)) { bv = ov; bi = oi; }
    }

    if (lane == 0) {
        int base = n*TOPK + j;
        if (!valid) {
            g_valid[base] = 0; g_label[base] = 0; g_score[base] = 0.f;
            g_meta[base] = make_float4(0.f, 0.f, 0.f, 0.f);
            #pragma unroll
            for (int q = 0; q < 8; q++) g_corners[base*8 + q] = 0.f;
            return;
        }
        const float* rp = reg + (size_t)n*4*KLOC + loc;
        float r0 = rp[0], r1 = rp[KLOC], r2 = rp[2*(size_t)KLOC], r3 = rp[3*(size_t)KLOC];
        const float* ap2 = anchors + ((size_t)n*KLOC + loc)*5;
        float acx = ap2[0], acy = ap2[1], aw = ap2[2], ah = ap2[3];
        float dx = r0/10.0f, dy = r1/10.0f;
        float dw = fminf(fmaxf(r2/5.0f, -10.0f), 4.0f);
        float dh = fminf(fmaxf(r3/5.0f, -10.0f), 4.0f);
        float cx = dx*aw + acx, cy = dy*ah + acy;
        float pw = aw*expf(dw), ph = ah*expf(dh);
        bool v2 = (pw >= 0.0f) && (ph >= 0.0f);
        float ang = (float)bi - 90.0f;
        float t = ang * 0.017453292519943295f;
        float c = cosf(t), s = sinf(t);
        const float oxm[4] = {1.f,-1.f,-1.f,1.f};
        const float oym[4] = {1.f, 1.f,-1.f,-1.f};
        #pragma unroll
        for (int q = 0; q < 4; q++) {
            float ox = oxm[q]*(pw*0.5f), oy = oym[q]*(ph*0.5f);
            g_corners[base*8 + 2*q]     = cx + ox*c - oy*s;
            g_corners[base*8 + 2*q + 1] = cy + ox*s + oy*c;
        }
        g_meta[base]  = make_float4(cx, cy, 0.5f*sqrtf(pw*pw + ph*ph) + 1.0f, pw*ph);
        g_score[base] = v2 ? sqrtf(fmaxf(topv, 0.f)) : 0.f;
        g_label[base] = cls + 1;
        g_valid[base] = v2 ? 1 : 0;
    }
}

// ---------------- rotated quad intersection (mirrors reference Sutherland-Hodgman) ----------------
__device__ float quad_inter_area(const float* c1, const float* c2) {
    float px[16], py[16];
    #pragma unroll
    for (int q = 0; q < 16; q++) { px[q] = 0.f; py[q] = 0.f; }
    #pragma unroll
    for (int q = 0; q < 4; q++) { px[q] = c1[2*q]; py[q] = c1[2*q+1]; }
    int nv = 4;
    for (int e = 0; e < 4; e++) {
        float p1x = c2[2*e], p1y = c2[2*e+1];
        int e2 = (e + 1) & 3;
        float ex = c2[2*e2]   - p1x;
        float ey = c2[2*e2+1] - p1y;
        float d[16];
        #pragma unroll
        for (int q = 0; q < 16; q++) d[q] = ex*(py[q]-p1y) - ey*(px[q]-p1x);
        float ox[16], oy[16];
        #pragma unroll
        for (int q = 0; q < 16; q++) { ox[q] = 0.f; oy[q] = 0.f; }
        int m = 0;
        for (int ii = 0; ii < 8; ii++) {
            int jj = (ii == nv-1) ? 0 : ii+1;
            float dc = d[ii], dn = d[jj];
            float denom = dc - dn;
            if (fabsf(denom) < 1e-8f) denom = 1e-8f;
            float tp = dc / denom;
            float ipx = px[ii] + tp*(px[jj]-px[ii]);
            float ipy = py[ii] + tp*(py[jj]-py[ii]);
            bool act = ii < nv;
            if (act && dc >= 0.f)                  { ox[m] = px[ii]; oy[m] = py[ii]; m++; }
            if (act && ((dc >= 0.f) != (dn >= 0.f))) { ox[m] = ipx;   oy[m] = ipy;   m++; }
        }
        #pragma unroll
        for (int q = 0; q < 16; q++) { px[q] = ox[q]; py[q] = oy[q]; }
        nv = m;
    }
    float s = 0.f;
    for (int ii = 0; ii < 16; ii++) {
        int jj = (ii == nv-1) ? 0 : ii+1;
        if (jj > 15) jj = 15;                 // jax gather clamp
        if (ii < nv) s += px[ii]*py[jj] - px[jj]*py[ii];
    }
    return 0.5f*fabsf(s);
}

// ---------------- K6: suppression bit matrix (thread = (i, 32-j word)) ----------------
__global__ void kIoU() {
    int n = blockIdx.y;
    __shared__ float  s_cor[TOPK*8];
    __shared__ float4 s_meta[TOPK];
    __shared__ int    s_lab[TOPK];
    for (int idx = threadIdx.x; idx < TOPK*8; idx += blockDim.x)
        s_cor[idx] = g_corners[(size_t)n*TOPK*8 + idx];
    for (int idx = threadIdx.x; idx < TOPK; idx += blockDim.x) {
        int base = n*TOPK + idx;
        s_meta[idx] = g_meta[base];
        s_lab[idx]  = g_valid[base] ? g_label[base] : 0;
    }
    __syncthreads();
    int t = blockIdx.x*blockDim.x + threadIdx.x;
    if (t >= TOPK*NWORDS) return;
    int i = t / NWORDS, w = t % NWORDS;
    unsigned int bitsOut = 0u;
    int li = s_lab[i];
    if (li != 0) {
        float4 mi = s_meta[i];
        float c1[8];
        #pragma unroll
        for (int q = 0; q < 8; q++) c1[q] = s_cor[i*8 + q];
        int j0 = w*32;
        int j1 = j0 + 32; if (j1 > TOPK) j1 = TOPK;
        int js = (j0 > i+1) ? j0 : (i+1);
        for (int j = js; j < j1; j++) {
            if (s_lab[j] != li) continue;
            float4 mj = s_meta[j];
            float ddx = mi.x - mj.x, ddy = mi.y - mj.y;
            float rr = mi.z + mj.z;
            if (ddx*ddx + ddy*ddy > rr*rr) continue;    // exact no-overlap reject
            float inter = quad_inter_area(c1, &s_cor[j*8]);
            float iou = inter / (mi.w + mj.w - inter + 1e-7f);
            if (iou > 0.4f) bitsOut |= 1u << (j - j0);
        }
    }
    g_sup[(size_t)n*TOPK*NWORDS + t] = bitsOut;
}

// ---------------- K7: greedy NMS (sparse rows) + output ----------------
__global__ void kNmsOut(float* __restrict__ out) {
    int n = blockIdx.x;
    int tid = threadIdx.x;   // 512 threads
    __shared__ unsigned int  s_sup[TOPK*NWORDS];
    __shared__ unsigned int  s_keep[NWORDS];
    __shared__ int           s_list[TOPK];
    __shared__ int           s_R;
    __shared__ unsigned char s_rowAny[TOPK];
    __shared__ int           s_wpref[NWORDS+1];

    for (int idx = tid; idx < TOPK*NWORDS; idx += blockDim.x)
        s_sup[idx] = g_sup[(size_t)n*TOPK*NWORDS + idx];
    {
        int j = tid;
        int flag = (j < TOPK) ? g_valid[n*TOPK + j] : 0;
        unsigned int bal = __ballot_sync(0xffffffffu, flag != 0);
        if ((tid & 31) == 0 && (tid >> 5) < NWORDS) s_keep[tid >> 5] = bal;
    }
    __syncthreads();
    if (tid < TOPK) {
        unsigned int any = 0;
        #pragma unroll
        for (int w = 0; w < NWORDS; w++) any |= s_sup[tid*NWORDS + w];
        s_rowAny[tid] = any ? 1 : 0;
    }
    __syncthreads();
    if (tid < 32) {
        // build ascending list of rows with nonzero suppression
        int cnt = 0;
        for (int g = 0; g < NWORDS; g++) {
            int i = g*32 + tid;
            int f = (i < TOPK) ? (int)s_rowAny[i] : 0;
            unsigned int bal = __ballot_sync(0xffffffffu, f);
            if (f) s_list[cnt + __popc(bal & ((1u << tid) - 1u))] = i;
            cnt += __popc(bal);
        }
        if (tid == 0) s_R = cnt;
        __syncwarp();
        // serial greedy over active rows; keep words live in lanes 0..12
        unsigned int kw = (tid < NWORDS) ? s_keep[tid] : 0u;
        int R = s_R;
        for (int r = 0; r < R; r++) {
            int i = s_list[r];
            unsigned int ow = __shfl_sync(0xffffffffu, kw, i >> 5);
            if ((ow >> (i & 31)) & 1u) {
                if (tid < NWORDS) kw &= ~s_sup[i*NWORDS + tid];
            }
        }
        if (tid < NWORDS) s_keep[tid] = kw;
    }
    __syncthreads();
    if (tid == 0) {
        int acc = 0;
        for (int w = 0; w < NWORDS; w++) { s_wpref[w] = acc; acc += __popc(s_keep[w]); }
        s_wpref[NWORDS] = acc;
    }
    __syncthreads();
    int kcount = s_wpref[NWORDS]; if (kcount > POSTN) kcount = POSTN;
    if (tid < TOPK) {
        int j = tid;
        unsigned int w = s_keep[j >> 5];
        if ((w >> (j & 31)) & 1u) {
            int rank = s_wpref[j >> 5] + __popc(w & ((1u << (j & 31)) - 1u));
            if (rank < POSTN) {
                float* row = out + ((size_t)n*POSTN + rank)*11;
                const float* c = g_corners + ((size_t)n*TOPK + j)*8;
                #pragma unroll
                for (int q = 0; q < 8; q++) row[q] = c[q];
                row[8]  = g_score[n*TOPK + j];
                row[9]  = (float)g_label[n*TOPK + j];
                row[10] = 1.0f;
            }
        }
    }
    for (int idx = tid; idx < (POSTN - kcount)*11; idx += blockDim.x)
        out[((size_t)n*POSTN + kcount)*11 + idx] = 0.0f;
}

// ---------------- launch ----------------
extern "C" void kernel_launch(void* const* d_in, const int* in_sizes, int n_in,
                              void* d_out, int out_size) {
    const float* box_cls = (const float*)d_in[0];
    const float* box_reg = (const float*)d_in[1];
    const float* ctr     = (const float*)d_in[2];
    const float* angle   = (const float*)d_in[3];
    const float* anchors = (const float*)d_in[4];
    float* out = (float*)d_out;
    (void)in_sizes; (void)n_in; (void)out_size;

    cudaFuncSetAttribute(kSort, cudaFuncAttributeMaxDynamicSharedMemorySize, CAP*8);

    kInit   <<<1024, 256>>>(ctr);
    kHist   <<<dim3(240, NIMG), 256>>>(box_cls);
    kThresh <<<NIMG, 256>>>();
    kCollect<<<dim3(240, NIMG), 256>>>(box_cls);
    kSort   <<<NIMG, 1024, CAP*8>>>();
    kDecode <<<dim3(50, NIMG), 256>>>(angle, box_reg, anchors);
    kIoU    <<<dim3((TOPK*NWORDS + 255)/256, NIMG), 256>>>();
    kNmsOut <<<NIMG, 512>>>(out);
}